// round 9
// baseline (speedup 1.0000x reference)
#include <cuda_runtime.h>
#include <cuda_fp16.h>
#include <cstdint>

#define N_NODES 50000
#define N_EDGES 800000
#define D 128
#define D4 (D / 4)
#define FULL 0xffffffffu
#define SCAN_B 1024
#define N_BLKS ((N_NODES + SCAN_B - 1) / SCAN_B)   // 49
#define N_TILES ((N_NODES + 63) / 64)              // 782
#define FUSED_GRID (N_TILES / 2)                   // 391, 2 tiles per block

// Static device scratch (no allocation; zero-initialized at load).
__device__ int   g_deg[N_NODES];
__device__ int   g_off[N_NODES + 1];
__device__ int   g_cursor[N_NODES];
__device__ int   g_csr[N_EDGES];
__device__ int   g_scan_flag[64];            // decoupled-lookback: total+1, 0 = not ready
__device__ uint4 g_feat_h[N_NODES * 16];     // fp16 feature rows (256B each)
__device__ uint2 g_Wh[D * D / 4];            // fp16 W, row-major [k][n]
__device__ uint4 g_zero16[16];               // 256B zeros, never written

// ---------------------------------------------------------------------------
// K1: prep — feature f32->f16, W f32->f16, in-degree histogram, flag clear.
// g_deg cleared by the PREVIOUS execution's fused kernel (zero at load).
// ---------------------------------------------------------------------------
__global__ void __launch_bounds__(256) prep_kernel(const float* __restrict__ feature,
                                                   const float* __restrict__ W,
                                                   const int* __restrict__ edge_dst) {
    int i = blockIdx.x * blockDim.x + threadIdx.x;
    if (i < N_NODES * D4) {
        float4 v = __ldg(reinterpret_cast<const float4*>(feature) + i);
        __half2 lo = __floats2half2_rn(v.x, v.y);
        __half2 hi = __floats2half2_rn(v.z, v.w);
        uint2 p;
        p.x = *reinterpret_cast<unsigned*>(&lo);
        p.y = *reinterpret_cast<unsigned*>(&hi);
        reinterpret_cast<uint2*>(g_feat_h)[i] = p;
    }
    if (i < D * D / 4) {
        float4 v = __ldg(reinterpret_cast<const float4*>(W) + i);
        __half2 lo = __floats2half2_rn(v.x, v.y);
        __half2 hi = __floats2half2_rn(v.z, v.w);
        uint2 p;
        p.x = *reinterpret_cast<unsigned*>(&lo);
        p.y = *reinterpret_cast<unsigned*>(&hi);
        g_Wh[i] = p;
    }
    if (i < 64) g_scan_flag[i] = 0;
    if (i < N_EDGES / 4) {
        int4 d = __ldg(reinterpret_cast<const int4*>(edge_dst) + i);
        atomicAdd(&g_deg[d.x], 1);
        atomicAdd(&g_deg[d.y], 1);
        atomicAdd(&g_deg[d.z], 1);
        atomicAdd(&g_deg[d.w], 1);
    }
}

// ---------------------------------------------------------------------------
// K2: single-pass exclusive scan, decoupled lookback (49 blocks, all
// resident). Block total published as flag = total+1 (single atomic word).
// Warp 1 sums predecessor totals while warp 0 finishes the local scan.
// ---------------------------------------------------------------------------
__global__ void __launch_bounds__(SCAN_B) scan_kernel() {
    __shared__ int s_wsum[32];
    __shared__ int s_base;
    int t = threadIdx.x, wid = t >> 5, lane = t & 31;
    int i = blockIdx.x * SCAN_B + t;
    int v = (i < N_NODES) ? g_deg[i] : 0;

    // inclusive warp scan
    int x = v;
    #pragma unroll
    for (int d = 1; d < 32; d <<= 1) {
        int y = __shfl_up_sync(FULL, x, d);
        if (lane >= d) x += y;
    }
    if (lane == 31) s_wsum[wid] = x;
    __syncthreads();

    if (wid == 0) {
        int w = s_wsum[lane];
        int xx = w;
        #pragma unroll
        for (int d = 1; d < 32; d <<= 1) {
            int y = __shfl_up_sync(FULL, xx, d);
            if (lane >= d) xx += y;
        }
        s_wsum[lane] = xx - w;                       // exclusive warp offset
        if (lane == 31)
            atomicExch(&g_scan_flag[blockIdx.x], xx + 1);   // publish total
    } else if (wid == 1) {
        // lookback: sum totals of blocks < blockIdx.x (each <= 48 of them)
        int sum = 0;
        for (int tt = lane; tt < (int)blockIdx.x; tt += 32) {
            int f;
            do { f = atomicAdd(&g_scan_flag[tt], 0); } while (f == 0);
            sum += f - 1;
        }
        #pragma unroll
        for (int d = 16; d >= 1; d >>= 1) sum += __shfl_xor_sync(FULL, sum, d);
        if (lane == 0) s_base = sum;
    }
    __syncthreads();

    if (i < N_NODES) {
        int off = (x - v) + s_wsum[wid] + s_base;
        g_off[i] = off;
        g_cursor[i] = off;
    }
    if (i == 0) g_off[N_NODES] = N_EDGES;
}

// ---------------------------------------------------------------------------
// K3: bucket fill — 8 edges/thread; all 8 atomics issued before the 8 stores
// (MLP=8 on the atomic-return chains).
// ---------------------------------------------------------------------------
__global__ void __launch_bounds__(256) bucket_kernel(const int* __restrict__ edge_src,
                                                     const int* __restrict__ edge_dst) {
    int i = blockIdx.x * blockDim.x + threadIdx.x;
    if (i < N_EDGES / 8) {
        int4 d0 = __ldg(reinterpret_cast<const int4*>(edge_dst) + 2 * i);
        int4 d1 = __ldg(reinterpret_cast<const int4*>(edge_dst) + 2 * i + 1);
        int4 s0 = __ldg(reinterpret_cast<const int4*>(edge_src) + 2 * i);
        int4 s1 = __ldg(reinterpret_cast<const int4*>(edge_src) + 2 * i + 1);
        int p0 = atomicAdd(&g_cursor[d0.x], 1);
        int p1 = atomicAdd(&g_cursor[d0.y], 1);
        int p2 = atomicAdd(&g_cursor[d0.z], 1);
        int p3 = atomicAdd(&g_cursor[d0.w], 1);
        int p4 = atomicAdd(&g_cursor[d1.x], 1);
        int p5 = atomicAdd(&g_cursor[d1.y], 1);
        int p6 = atomicAdd(&g_cursor[d1.z], 1);
        int p7 = atomicAdd(&g_cursor[d1.w], 1);
        g_csr[p0] = s0.x; g_csr[p1] = s0.y; g_csr[p2] = s0.z; g_csr[p3] = s0.w;
        g_csr[p4] = s1.x; g_csr[p5] = s1.y; g_csr[p6] = s1.z; g_csr[p7] = s1.w;
    }
}

// ---------------------------------------------------------------------------
// K4: fused aggregate + tensor-core GEMM + bias + relu.
// Grid = 391 blocks, each handles tiles {bid, bid+391} (all resident, zero
// wave imbalance). Per tile: 8 warps each gather-aggregate 8 nodes (half-warp
// per fp16 row, fp32 accumulate) straight into the swizzled smem A tile, then
// mma.m16n8k16 against W (staged to smem ONCE per block). h never touches
// global memory. Also clears g_deg for the next execution.
// ---------------------------------------------------------------------------
__device__ __forceinline__ void acc8(float* acc, uint4 a) {
    float2 f0 = __half22float2(*reinterpret_cast<__half2*>(&a.x));
    float2 f1 = __half22float2(*reinterpret_cast<__half2*>(&a.y));
    float2 f2 = __half22float2(*reinterpret_cast<__half2*>(&a.z));
    float2 f3 = __half22float2(*reinterpret_cast<__half2*>(&a.w));
    acc[0] += f0.x; acc[1] += f0.y; acc[2] += f1.x; acc[3] += f1.y;
    acc[4] += f2.x; acc[5] += f2.y; acc[6] += f3.x; acc[7] += f3.y;
}

__global__ void __launch_bounds__(256) fused_kernel(const float* __restrict__ b,
                                                    float* __restrict__ out) {
    __shared__ uint4 sW[D * 16];    // 32 KB swizzled fp16 W
    __shared__ uint4 sA[64 * 16];   // 16 KB swizzled fp16 h tile

    int tid = threadIdx.x;
    int warp = tid >> 5;
    int lane = tid & 31;
    int half = lane >> 4;
    int hl   = lane & 15;
    int warp_m = warp >> 1;
    int warp_n = warp & 1;
    int lt = lane >> 3;
    int lj = lane & 7;

    // Clear g_deg for the next execution's histogram (stream-ordered).
    {
        int gid = blockIdx.x * 256 + tid;
        if (gid < N_NODES) g_deg[gid] = 0;
    }

    // Stage W once per block.
    #pragma unroll
    for (int it = 0; it < 8; it++) {
        int seg = tid + it * 256;
        int row = seg >> 4, u = seg & 15;
        sW[row * 16 + (u ^ (row & 7))] = reinterpret_cast<const uint4*>(g_Wh)[seg];
    }

    const uint4* fh = g_feat_h;

    for (int tile = blockIdx.x; tile < N_TILES; tile += FUSED_GRID) {
        int row0 = tile * 64;
        __syncthreads();   // prev gemm done reading sA; W visible on first iter

        // ---- aggregate 8 nodes per warp into sA ----
        for (int r = 0; r < 8; r++) {
            int lrow = warp * 8 + r;
            int node = row0 + lrow;
            float acc[8];
            #pragma unroll
            for (int q = 0; q < 8; q++) acc[q] = 0.f;

            if (node < N_NODES) {
                int j0 = g_off[node];
                int len = g_off[node + 1] - j0;
                for (int base = 0; base < len; base += 32) {
                    int nb = len - base; if (nb > 32) nb = 32;
                    int myidx = 0;
                    if (base + lane < len) myidx = g_csr[j0 + base + lane];
                    int t = 0;
                    for (; t + 8 <= nb; t += 8) {
                        int s0 = __shfl_sync(FULL, myidx, t + 0 + half);
                        int s1 = __shfl_sync(FULL, myidx, t + 2 + half);
                        int s2 = __shfl_sync(FULL, myidx, t + 4 + half);
                        int s3 = __shfl_sync(FULL, myidx, t + 6 + half);
                        uint4 a0 = __ldg(fh + (size_t)s0 * 16 + hl);
                        uint4 a1 = __ldg(fh + (size_t)s1 * 16 + hl);
                        uint4 a2 = __ldg(fh + (size_t)s2 * 16 + hl);
                        uint4 a3 = __ldg(fh + (size_t)s3 * 16 + hl);
                        acc8(acc, a0); acc8(acc, a1); acc8(acc, a2); acc8(acc, a3);
                    }
                    for (; t + 2 <= nb; t += 2) {
                        int s0 = __shfl_sync(FULL, myidx, t + half);
                        uint4 a0 = __ldg(fh + (size_t)s0 * 16 + hl);
                        acc8(acc, a0);
                    }
                    if (t < nb) {
                        int s0 = __shfl_sync(FULL, myidx, t);
                        const uint4* p = half ? (const uint4*)g_zero16
                                              : (fh + (size_t)s0 * 16);
                        uint4 a0 = __ldg(p + hl);
                        acc8(acc, a0);
                    }
                }
            }
            #pragma unroll
            for (int q = 0; q < 8; q++)
                acc[q] += __shfl_xor_sync(FULL, acc[q], 16);

            if (half == 0) {
                __half2 h0 = __floats2half2_rn(acc[0], acc[1]);
                __half2 h1 = __floats2half2_rn(acc[2], acc[3]);
                __half2 h2 = __floats2half2_rn(acc[4], acc[5]);
                __half2 h3 = __floats2half2_rn(acc[6], acc[7]);
                uint4 p;
                p.x = *reinterpret_cast<unsigned*>(&h0);
                p.y = *reinterpret_cast<unsigned*>(&h1);
                p.z = *reinterpret_cast<unsigned*>(&h2);
                p.w = *reinterpret_cast<unsigned*>(&h3);
                sA[lrow * 16 + (hl ^ (lrow & 7))] = p;
            }
        }
        __syncthreads();

        // ---- tensor-core GEMM on the tile ----
        unsigned sWb = (unsigned)__cvta_generic_to_shared(sW);
        unsigned sAb = (unsigned)__cvta_generic_to_shared(sA);

        float d[8][4];
        #pragma unroll
        for (int t = 0; t < 8; t++)
            #pragma unroll
            for (int c = 0; c < 4; c++) d[t][c] = 0.f;

        #pragma unroll
        for (int k = 0; k < 8; k++) {
            unsigned a0, a1, a2, a3;
            {
                int rr = warp_m * 16 + ((lt & 1) << 3) + lj;
                int u  = (k << 1) + (lt >> 1);
                unsigned addr = sAb + ((rr << 4) + (u ^ (rr & 7))) * 16;
                asm volatile("ldmatrix.sync.aligned.m8n8.x4.shared.b16 {%0,%1,%2,%3}, [%4];"
                             : "=r"(a0), "=r"(a1), "=r"(a2), "=r"(a3) : "r"(addr));
            }
            #pragma unroll
            for (int p = 0; p < 4; p++) {
                int n0 = warp_n * 64 + p * 16;
                int rr = (k << 4) + ((lt & 1) << 3) + lj;
                int u  = (n0 >> 3) + (lt >> 1);
                unsigned addr = sWb + ((rr << 4) + (u ^ (rr & 7))) * 16;
                unsigned b00, b01, b10, b11;
                asm volatile("ldmatrix.sync.aligned.m8n8.x4.trans.shared.b16 {%0,%1,%2,%3}, [%4];"
                             : "=r"(b00), "=r"(b01), "=r"(b10), "=r"(b11) : "r"(addr));
                int t0 = 2 * p, t1 = 2 * p + 1;
                asm volatile("mma.sync.aligned.m16n8k16.row.col.f32.f16.f16.f32 "
                             "{%0,%1,%2,%3}, {%4,%5,%6,%7}, {%8,%9}, {%0,%1,%2,%3};"
                             : "+f"(d[t0][0]), "+f"(d[t0][1]), "+f"(d[t0][2]), "+f"(d[t0][3])
                             : "r"(a0), "r"(a1), "r"(a2), "r"(a3), "r"(b00), "r"(b01));
                asm volatile("mma.sync.aligned.m16n8k16.row.col.f32.f16.f16.f32 "
                             "{%0,%1,%2,%3}, {%4,%5,%6,%7}, {%8,%9}, {%0,%1,%2,%3};"
                             : "+f"(d[t1][0]), "+f"(d[t1][1]), "+f"(d[t1][2]), "+f"(d[t1][3])
                             : "r"(a0), "r"(a1), "r"(a2), "r"(a3), "r"(b10), "r"(b11));
            }
        }

        // epilogue: bias + relu + f32 stores
        int r = lane >> 2;
        int c = (lane & 3) * 2;
        #pragma unroll
        for (int t = 0; t < 8; t++) {
            int col = warp_n * 64 + t * 8 + c;
            float2 bb = *reinterpret_cast<const float2*>(b + col);
            int grow = row0 + warp_m * 16 + r;
            if (grow < N_NODES) {
                float2 o;
                o.x = fmaxf(d[t][0] + bb.x, 0.f);
                o.y = fmaxf(d[t][1] + bb.y, 0.f);
                *reinterpret_cast<float2*>(out + (size_t)grow * D + col) = o;
            }
            int grow2 = grow + 8;
            if (grow2 < N_NODES) {
                float2 o;
                o.x = fmaxf(d[t][2] + bb.x, 0.f);
                o.y = fmaxf(d[t][3] + bb.y, 0.f);
                *reinterpret_cast<float2*>(out + (size_t)grow2 * D + col) = o;
            }
        }
    }
}

// ---------------------------------------------------------------------------
// Inputs: feature f32[50000,128], edge_src i32[800000], edge_dst i32[800000],
// W f32[128,128], b f32[128]. Output f32[50000,128].
// ---------------------------------------------------------------------------
extern "C" void kernel_launch(void* const* d_in, const int* in_sizes, int n_in,
                              void* d_out, int out_size) {
    const float* feature  = (const float*)d_in[0];
    const int*   edge_src = (const int*)d_in[1];
    const int*   edge_dst = (const int*)d_in[2];
    const float* W        = (const float*)d_in[3];
    const float* b        = (const float*)d_in[4];
    float* out = (float*)d_out;

    prep_kernel<<<(N_NODES * D4 + 255) / 256, 256>>>(feature, W, edge_dst);
    scan_kernel<<<N_BLKS, SCAN_B>>>();
    bucket_kernel<<<(N_EDGES / 8 + 255) / 256, 256>>>(edge_src, edge_dst);
    fused_kernel<<<FUSED_GRID, 256>>>(b, out);
}